// round 12
// baseline (speedup 1.0000x reference)
#include <cuda_runtime.h>
#include <cuda_fp16.h>
#include <math.h>
#include <stdint.h>

#define TT   2048
#define HID  4096
#define NH   32
#define NKV  8
#define HD   128
#define QSZ  (NH * HD)          // 4096
#define KVSZ (NKV * HD)         // 1024
#define QKVO (QSZ + 2 * KVSZ)   // 6144

// ---------------- device scratch (allocation-free) ----------------
__device__ uint32_t g_qh[TT * QSZ / 2];        // normed+roped+scaled q (half2)
__device__ uint32_t g_kh[TT * KVSZ / 2];       // normed+roped k (half2)
__device__ uint32_t g_vh[TT * KVSZ / 2];       // v (half2)
__device__ uint32_t g_attnq16[TT * QSZ / 2];   // attn out, fp16 quad layout
__device__ uint32_t g_h16[TT * HID / 2];       // hidden, fp16 quad layout
__device__ uint32_t g_wqkv16[QKVO * HID / 2];  // w_qkv,  fp16 quad layout
__device__ uint32_t g_wo16[HID * QSZ / 2];     // w_o,    fp16 quad layout
__device__ float    g_rope[TT * 64];           // cos/sin table per (t, i)

// ---------------- helpers ----------------
__device__ __forceinline__ uint32_t packh2(float a, float b) {
    __half2 h = __floats2half2_rn(a, b);
    return *(uint32_t*)&h;
}
__device__ __forceinline__ void mma_f16(float* d, const uint32_t* a, const uint32_t* b) {
    asm volatile(
        "mma.sync.aligned.m16n8k16.row.col.f32.f16.f16.f32 "
        "{%0,%1,%2,%3},{%4,%5,%6,%7},{%8,%9},{%0,%1,%2,%3};"
        : "+f"(d[0]), "+f"(d[1]), "+f"(d[2]), "+f"(d[3])
        : "r"(a[0]), "r"(a[1]), "r"(a[2]), "r"(a[3]), "r"(b[0]), "r"(b[1]));
}
__device__ __forceinline__ void cp16(uint32_t smem_addr, const void* gptr) {
    asm volatile("cp.async.cg.shared.global [%0], [%1], 16;"
                 :: "r"(smem_addr), "l"(gptr));
}
__device__ __forceinline__ void ldsm_x2_trans(uint32_t& r0, uint32_t& r1, uint32_t addr) {
    asm volatile("ldmatrix.sync.aligned.m8n8.x2.trans.shared.b16 {%0,%1}, [%2];"
                 : "=r"(r0), "=r"(r1) : "r"(addr));
}

// ---------------- rope cos/sin table ----------------
__global__ __launch_bounds__(256) void rope_table_kernel()
{
    const int idx = blockIdx.x * 256 + threadIdx.x;   // T*32
    const int t = idx >> 5, i = idx & 31;
    const float freq = powf(10000.0f, -(float)i * (1.0f / 32.0f));
    float sn, cs;
    sincosf((float)t * freq, &sn, &cs);
    g_rope[t * 64 + 2 * i]     = cs;
    g_rope[t * 64 + 2 * i + 1] = sn;
}

// ---------------- convert f32 row-major -> fp16 quad layout -----------------
__global__ __launch_bounds__(256) void conv_quad_h(
    const float* __restrict__ src, uint32_t* __restrict__ dst, int R, int C)
{
    const int q = blockIdx.x * 256 + threadIdx.x;
    const int lane = q & 31;
    const int t2 = q >> 5;
    const int row16 = t2 % (R >> 4);
    const int k16   = t2 / (R >> 4);
    const int g = lane >> 2, t = lane & 3;
    const size_t r = row16 * 16 + g;
    const size_t c = k16 * 16 + 2 * t;
    const float* p0 = src + r * C + c;
    const float* p1 = src + (r + 8) * C + c;
    uint4 o;
    o.x = packh2(p0[0], p0[1]);
    o.y = packh2(p1[0], p1[1]);
    o.z = packh2(p0[8], p0[9]);
    o.w = packh2(p1[8], p1[9]);
    *(uint4*)&dst[(size_t)q * 4] = o;
}

// ---------------- fp16 quad GEMM: 128x128 tile, 2 CTA/SM, 4-stage -----------
#define GEMM_SMEM0 (4 * 16384)
#define GEMM_SMEM1 (128 * 130 * 4)   // epilogue staging (>= pipeline smem)
template <int EPI>
__global__ __launch_bounds__(256, 2) void gemm_h16(
    const uint32_t* __restrict__ Aq, const uint32_t* __restrict__ Bq,
    const float* __restrict__ bias, float* __restrict__ C,
    const float* __restrict__ qnw, const float* __restrict__ knw,
    int M, int N, int K)
{
    extern __shared__ uint32_t sm[];
    const int tid  = threadIdx.x;
    const int lane = tid & 31;
    const int warp = tid >> 5;
    const int wm = (warp >> 2) * 64;
    const int wn = (warp & 3) * 32;
    const int m0 = blockIdx.y * 128, n0 = blockIdx.x * 128;
    const int g = lane >> 2, t4 = lane & 3;

    const uint32_t smem_base = (uint32_t)__cvta_generic_to_shared(sm);
    const uint32_t dA0 = smem_base + (warp * 32 + lane) * 16;
    const uint32_t dA1 = smem_base + ((8 + warp) * 32 + lane) * 16;
    const uint32_t dB0 = smem_base + 8192 + (warp * 32 + lane) * 16;
    const uint32_t dB1 = smem_base + 8192 + ((8 + warp) * 32 + lane) * 16;
    const uint32_t* srcA = Aq + (size_t)(m0 / 16 + warp) * 128 + lane * 4;
    const uint32_t* srcB = Bq + (size_t)(n0 / 16 + warp) * 128 + lane * 4;
    const size_t sA = (size_t)M * 8;
    const size_t sB = (size_t)N * 8;

    float acc[4][4][4];
#pragma unroll
    for (int i = 0; i < 4; i++)
#pragma unroll
        for (int j = 0; j < 4; j++)
#pragma unroll
            for (int c = 0; c < 4; c++) acc[i][j][c] = 0.f;

#define ISSUE(stage, k16s)                                               \
    do {                                                                 \
        const uint32_t so = (stage) * 16384;                             \
        cp16(dA0 + so, srcA + (size_t)(k16s) * sA);                      \
        cp16(dA1 + so, srcA + (size_t)((k16s) + 1) * sA);                \
        cp16(dB0 + so, srcB + (size_t)(k16s) * sB);                      \
        cp16(dB1 + so, srcB + (size_t)((k16s) + 1) * sB);                \
        asm volatile("cp.async.commit_group;");                          \
    } while (0)

    const int nkt = K / 32;
    ISSUE(0, 0);
    ISSUE(1, 2);
    ISSUE(2, 4);

    const int arb = (warp >> 2) * 4;
    const int bcb = (warp & 3) * 2;

    for (int i = 0; i < nkt; i++) {
        if (i + 1 < nkt) { asm volatile("cp.async.wait_group 2;"); }
        else             { asm volatile("cp.async.wait_group 0;"); }
        __syncthreads();

        const int i3 = i + 3;
        if (i3 < nkt) ISSUE(i3 & 3, 2 * i3);

        const uint32_t* As = sm + (i & 3) * 4096;
        const uint32_t* Bs = As + 2048;
#pragma unroll
        for (int s = 0; s < 2; s++) {
            uint4 afq[4];
            const uint32_t* ab = As + ((s * 8 + arb) * 32 + lane) * 4;
#pragma unroll
            for (int mi = 0; mi < 4; mi++)
                afq[mi] = *(const uint4*)(ab + mi * 128);
            const uint32_t* bb = Bs + ((s * 8 + bcb) * 32 + lane) * 4;
            const uint4 bq0 = *(const uint4*)bb;
            const uint4 bq1 = *(const uint4*)(bb + 128);

            const uint32_t b0[2] = {bq0.x, bq0.z};
            const uint32_t b1[2] = {bq0.y, bq0.w};
            const uint32_t b2[2] = {bq1.x, bq1.z};
            const uint32_t b3[2] = {bq1.y, bq1.w};
#pragma unroll
            for (int mi = 0; mi < 4; mi++) {
                const uint32_t a[4] = {afq[mi].x, afq[mi].y, afq[mi].z, afq[mi].w};
                mma_f16(acc[mi][0], a, b0);
                mma_f16(acc[mi][1], a, b1);
                mma_f16(acc[mi][2], a, b2);
                mma_f16(acc[mi][3], a, b3);
            }
        }
    }
#undef ISSUE

    if (EPI == 0) {
#pragma unroll
        for (int mi = 0; mi < 4; mi++) {
            const int row = m0 + wm + mi * 16 + g;
#pragma unroll
            for (int ni = 0; ni < 4; ni++) {
                const int col = n0 + wn + ni * 8 + 2 * t4;
                float2 v0 = make_float2(acc[mi][ni][0], acc[mi][ni][1]);
                float2 v1 = make_float2(acc[mi][ni][2], acc[mi][ni][3]);
                *(float2*)&C[(size_t)row * N + col] = v0;
                *(float2*)&C[(size_t)(row + 8) * N + col] = v1;
            }
        }
        return;
    }

    // ---- EPI == 1: fused bias + RMSNorm + RoPE + fp16 pack ----
    float* stg = (float*)sm;    // [128][130]
    __syncthreads();
#pragma unroll
    for (int mi = 0; mi < 4; mi++) {
        const int row = wm + mi * 16 + g;
#pragma unroll
        for (int ni = 0; ni < 4; ni++) {
            const int col = wn + ni * 8 + 2 * t4;
            const float b0 = bias[n0 + col], b1 = bias[n0 + col + 1];
            stg[row * 130 + col]     = acc[mi][ni][0] + b0;
            stg[row * 130 + col + 1] = acc[mi][ni][1] + b1;
            stg[(row + 8) * 130 + col]     = acc[mi][ni][2] + b0;
            stg[(row + 8) * 130 + col + 1] = acc[mi][ni][3] + b1;
        }
    }
    __syncthreads();

    const int r = tid >> 1, h2 = tid & 1;
    const int tok = m0 + r;
    const int nh = n0 >> 7;
    float y[64];
    const float* rp = stg + r * 130 + h2 * 64;
#pragma unroll
    for (int i = 0; i < 32; i++) {
        float2 f = *(const float2*)(rp + 2 * i);
        y[2 * i] = f.x; y[2 * i + 1] = f.y;
    }
    float ssq = 0.f;
#pragma unroll
    for (int j = 0; j < 64; j++) ssq += y[j] * y[j];
    ssq += __shfl_xor_sync(0xffffffffu, ssq, 1);

    if (nh < 40) {
        const float rms = rsqrtf(ssq * (1.0f / HD) + 1e-5f);
        const float* wv = (nh < NH ? qnw : knw) + h2 * 64;
#pragma unroll
        for (int j = 0; j < 64; j++) y[j] *= rms * wv[j];
        if (h2 == 0) {
            const float* rt = g_rope + tok * 64;
#pragma unroll
            for (int d = 0; d < 32; d++) {
                const float cs = rt[2 * d], sn = rt[2 * d + 1];
                const float a0 = y[d] * cs - y[d + 32] * sn;
                const float a1 = y[d + 32] * cs + y[d] * sn;
                y[d] = a0; y[d + 32] = a1;
            }
        }
        if (nh < NH) {
#pragma unroll
            for (int j = 0; j < 64; j++) y[j] *= 0.0883883476483184f;
        }
    }

    uint32_t* dst;
    if (nh < NH)      dst = g_qh + (size_t)tok * (QSZ / 2) + nh * 64 + h2 * 32;
    else if (nh < 40) dst = g_kh + (size_t)tok * (KVSZ / 2) + (nh - NH) * 64 + h2 * 32;
    else              dst = g_vh + (size_t)tok * (KVSZ / 2) + (nh - 40) * 64 + h2 * 32;
#pragma unroll
    for (int u = 0; u < 8; u++) {
        uint4 o;
        o.x = packh2(y[8 * u + 0], y[8 * u + 1]);
        o.y = packh2(y[8 * u + 2], y[8 * u + 3]);
        o.z = packh2(y[8 * u + 4], y[8 * u + 5]);
        o.w = packh2(y[8 * u + 6], y[8 * u + 7]);
        ((uint4*)dst)[u] = o;
    }
}

// ---------------- fp16 tensor-core causal flash attention -------------------
// Q + P in registers; KV double-buffered via cp.async (latency overlap).
#define AQS 68
#define V_OFF (64 * AQS)
#define STG_W (2 * 64 * AQS)                 // words per stage (K+V)
#define ATTN_SMEM (2 * STG_W * 4)            // 69632 B -> occ 3

__global__ __launch_bounds__(128, 3) void attn_h16_kernel()
{
    extern __shared__ uint32_t smem_u[];
    const int tid  = threadIdx.x;
    const int lane = tid & 31;
    const int warp = tid >> 5;
    const int g    = lane >> 2;
    const int t4   = lane & 3;
    const int wq0  = warp * 16;
    const int bx = blockIdx.x, h = blockIdx.y, kvh = h >> 2;

    const uint32_t sb = (uint32_t)__cvta_generic_to_shared(smem_u);
    const uint32_t vb0 = sb + (V_OFF + (lane & 15) * AQS) * 4;

    // Q fragments, loop-invariant -> registers
    uint32_t qa[8][4];
    {
        const uint32_t* q0 = &g_qh[(size_t)(bx * 64 + wq0 + g) * (QSZ / 2) + h * 64];
        const uint32_t* q1 = &g_qh[(size_t)(bx * 64 + wq0 + g + 8) * (QSZ / 2) + h * 64];
#pragma unroll
        for (int kb = 0; kb < 8; kb++) {
            qa[kb][0] = q0[kb * 8 + t4];
            qa[kb][1] = q1[kb * 8 + t4];
            qa[kb][2] = q0[kb * 8 + t4 + 4];
            qa[kb][3] = q1[kb * 8 + t4 + 4];
        }
    }

#define KV_ISSUE(stg, kt)                                                     \
    do {                                                                      \
        _Pragma("unroll")                                                     \
        for (int j = 0; j < 8; j++) {                                         \
            const int i = tid + j * 128;                                      \
            const int r = i >> 4, w4 = (i & 15) << 2;                         \
            const size_t goff = (size_t)((kt) * 64 + r) * (KVSZ / 2)          \
                                + kvh * 64 + w4;                              \
            const uint32_t so = sb + ((stg) * STG_W + r * AQS + w4) * 4;      \
            cp16(so, &g_kh[goff]);                                            \
            cp16(so + V_OFF * 4, &g_vh[goff]);                                \
        }                                                                     \
        asm volatile("cp.async.commit_group;");                               \
    } while (0)

    float m0 = -1e30f, m1 = -1e30f, l0 = 0.f, l1 = 0.f;
    float acc_o[16][4];
#pragma unroll
    for (int nb = 0; nb < 16; nb++)
#pragma unroll
        for (int c = 0; c < 4; c++) acc_o[nb][c] = 0.f;

    KV_ISSUE(0, 0);

    for (int kt = 0; kt <= bx; kt++) {
        const int cur = kt & 1;
        __syncthreads();   // all warps done reading buffer cur^1 (iter kt-1)
        if (kt + 1 <= bx) {
            KV_ISSUE(cur ^ 1, kt + 1);
            asm volatile("cp.async.wait_group 1;");
        } else {
            asm volatile("cp.async.wait_group 0;");
        }
        __syncthreads();   // tile kt visible to all warps

        const uint32_t* Ks = smem_u + cur * STG_W;
        const uint32_t vb = vb0 + cur * STG_W * 4;

        // S = Q K^T
        float s[8][4];
#pragma unroll
        for (int nb = 0; nb < 8; nb++)
#pragma unroll
            for (int c = 0; c < 4; c++) s[nb][c] = 0.f;

#pragma unroll
        for (int kb = 0; kb < 8; kb++) {
#pragma unroll
            for (int nb = 0; nb < 8; nb++) {
                uint32_t b[2];
                b[0] = Ks[(nb * 8 + g) * AQS + kb * 8 + t4];
                b[1] = Ks[(nb * 8 + g) * AQS + kb * 8 + t4 + 4];
                mma_f16(s[nb], qa[kb], b);
            }
        }

        if (kt == bx) {
            const int r0 = wq0 + g, r1 = r0 + 8;
#pragma unroll
            for (int nb = 0; nb < 8; nb++) {
                const int c = nb * 8 + 2 * t4;
                if (c     > r0) s[nb][0] = -1e30f;
                if (c + 1 > r0) s[nb][1] = -1e30f;
                if (c     > r1) s[nb][2] = -1e30f;
                if (c + 1 > r1) s[nb][3] = -1e30f;
            }
        }

        // online softmax; pack P directly into PV A-fragments
        float mx0 = -1e30f, mx1 = -1e30f;
#pragma unroll
        for (int nb = 0; nb < 8; nb++) {
            mx0 = fmaxf(mx0, fmaxf(s[nb][0], s[nb][1]));
            mx1 = fmaxf(mx1, fmaxf(s[nb][2], s[nb][3]));
        }
        mx0 = fmaxf(mx0, __shfl_xor_sync(0xffffffffu, mx0, 1));
        mx0 = fmaxf(mx0, __shfl_xor_sync(0xffffffffu, mx0, 2));
        mx1 = fmaxf(mx1, __shfl_xor_sync(0xffffffffu, mx1, 1));
        mx1 = fmaxf(mx1, __shfl_xor_sync(0xffffffffu, mx1, 2));
        const float mn0 = fmaxf(m0, mx0), mn1 = fmaxf(m1, mx1);
        const float cr0 = __expf(m0 - mn0), cr1 = __expf(m1 - mn1);
        float rs0 = 0.f, rs1 = 0.f;
        uint32_t ph0[8], ph1[8];
#pragma unroll
        for (int nb = 0; nb < 8; nb++) {
            float p0 = __expf(s[nb][0] - mn0);
            float p1 = __expf(s[nb][1] - mn0);
            float p2 = __expf(s[nb][2] - mn1);
            float p3 = __expf(s[nb][3] - mn1);
            rs0 += p0 + p1; rs1 += p2 + p3;
            ph0[nb] = packh2(p0, p1);
            ph1[nb] = packh2(p2, p3);
        }
        rs0 += __shfl_xor_sync(0xffffffffu, rs0, 1);
        rs0 += __shfl_xor_sync(0xffffffffu, rs0, 2);
        rs1 += __shfl_xor_sync(0xffffffffu, rs1, 1);
        rs1 += __shfl_xor_sync(0xffffffffu, rs1, 2);
        l0 = l0 * cr0 + rs0; l1 = l1 * cr1 + rs1;
        m0 = mn0; m1 = mn1;

#pragma unroll
        for (int nb = 0; nb < 16; nb++) {
            acc_o[nb][0] *= cr0; acc_o[nb][1] *= cr0;
            acc_o[nb][2] *= cr1; acc_o[nb][3] *= cr1;
        }

        // O += P V
#pragma unroll
        for (int kb = 0; kb < 4; kb++) {
            const uint32_t a[4] = {ph0[2 * kb], ph1[2 * kb],
                                   ph0[2 * kb + 1], ph1[2 * kb + 1]};
            const uint32_t vkb = vb + kb * 16 * AQS * 4;
#pragma unroll
            for (int nb = 0; nb < 16; nb++) {
                uint32_t b[2];
                ldsm_x2_trans(b[0], b[1], vkb + nb * 16);
                mma_f16(acc_o[nb], a, b);
            }
        }
    }
#undef KV_ISSUE

    const float il0 = 1.0f / l0, il1 = 1.0f / l1;
    const int row16 = bx * 4 + warp;
#pragma unroll
    for (int nbp = 0; nbp < 8; nbp++) {
        const int nbe = 2 * nbp, nbo = 2 * nbp + 1;
        const int k16 = h * 8 + nbp;
        uint4 o;
        o.x = packh2(acc_o[nbe][0] * il0, acc_o[nbe][1] * il0);
        o.y = packh2(acc_o[nbe][2] * il1, acc_o[nbe][3] * il1);
        o.z = packh2(acc_o[nbo][0] * il0, acc_o[nbo][1] * il0);
        o.w = packh2(acc_o[nbo][2] * il1, acc_o[nbo][3] * il1);
        const size_t quad = ((size_t)k16 * (TT / 16) + row16) * 32 + lane;
        *(uint4*)&g_attnq16[quad * 4] = o;
    }
}

// ---------------- launch ----------------
extern "C" void kernel_launch(void* const* d_in, const int* in_sizes, int n_in,
                              void* d_out, int out_size)
{
    const float* hidden = (const float*)d_in[1];
    const float* w_qkv  = (const float*)d_in[2];
    const float* b_qkv  = (const float*)d_in[3];
    const float* qnw    = (const float*)d_in[4];
    const float* knw    = (const float*)d_in[5];
    const float* w_o    = (const float*)d_in[6];
    float* out = (float*)d_out;

    uint32_t *attnq_s, *h16_s, *wqkv16_s, *wo16_s;
    cudaGetSymbolAddress((void**)&attnq_s, g_attnq16);
    cudaGetSymbolAddress((void**)&h16_s, g_h16);
    cudaGetSymbolAddress((void**)&wqkv16_s, g_wqkv16);
    cudaGetSymbolAddress((void**)&wo16_s, g_wo16);

    // 0) operand conversion + rope table
    conv_quad_h<<<(TT * HID) / 2048, 256>>>(hidden, h16_s, TT, HID);
    conv_quad_h<<<(QKVO * HID) / 2048, 256>>>(w_qkv, wqkv16_s, QKVO, HID);
    conv_quad_h<<<(HID * QSZ) / 2048, 256>>>(w_o, wo16_s, HID, QSZ);
    rope_table_kernel<<<(TT * 32) / 256, 256>>>();

    cudaFuncSetAttribute(gemm_h16<1>,
                         cudaFuncAttributeMaxDynamicSharedMemorySize, GEMM_SMEM1);
    cudaFuncSetAttribute(gemm_h16<0>,
                         cudaFuncAttributeMaxDynamicSharedMemorySize, GEMM_SMEM0);

    // 1) QKV projection + fused bias/norm/rope/pack
    gemm_h16<1><<<dim3(QKVO / 128, TT / 128), 256, GEMM_SMEM1>>>(
        h16_s, wqkv16_s, b_qkv, nullptr, qnw, knw, TT, QKVO, HID);

    // 2) causal GQA flash attention (Q+P in regs, cp.async KV pipeline)
    cudaFuncSetAttribute(attn_h16_kernel,
                         cudaFuncAttributeMaxDynamicSharedMemorySize, ATTN_SMEM);
    attn_h16_kernel<<<dim3(TT / 64, NH), 128, ATTN_SMEM>>>();

    // 3) output projection
    gemm_h16<0><<<dim3(HID / 128, TT / 128), 256, GEMM_SMEM0>>>(
        attnq_s, wo16_s, nullptr, out, nullptr, nullptr, TT, HID, QSZ);
}

// round 14
// speedup vs baseline: 1.0404x; 1.0404x over previous
#include <cuda_runtime.h>
#include <cuda_fp16.h>
#include <math.h>
#include <stdint.h>

#define TT   2048
#define HID  4096
#define NH   32
#define NKV  8
#define HD   128
#define QSZ  (NH * HD)          // 4096
#define KVSZ (NKV * HD)         // 1024
#define QKVO (QSZ + 2 * KVSZ)   // 6144

// ---------------- device scratch (allocation-free) ----------------
__device__ uint32_t g_qh[TT * QSZ / 2];        // normed+roped+scaled q (half2)
__device__ uint32_t g_kh[TT * KVSZ / 2];       // normed+roped k (half2)
__device__ uint32_t g_vh[TT * KVSZ / 2];       // v (half2)
__device__ uint32_t g_attnq16[TT * QSZ / 2];   // attn out, fp16 quad layout
__device__ uint32_t g_h16[TT * HID / 2];       // hidden, fp16 quad layout
__device__ uint32_t g_wqkv16[QKVO * HID / 2];  // w_qkv,  fp16 quad layout
__device__ uint32_t g_wo16[HID * QSZ / 2];     // w_o,    fp16 quad layout
__device__ float    g_rope[TT * 64];           // cos/sin table per (t, i)

// ---------------- helpers ----------------
__device__ __forceinline__ uint32_t packh2(float a, float b) {
    __half2 h = __floats2half2_rn(a, b);
    return *(uint32_t*)&h;
}
__device__ __forceinline__ void mma_f16(float* d, const uint32_t* a, const uint32_t* b) {
    asm volatile(
        "mma.sync.aligned.m16n8k16.row.col.f32.f16.f16.f32 "
        "{%0,%1,%2,%3},{%4,%5,%6,%7},{%8,%9},{%0,%1,%2,%3};"
        : "+f"(d[0]), "+f"(d[1]), "+f"(d[2]), "+f"(d[3])
        : "r"(a[0]), "r"(a[1]), "r"(a[2]), "r"(a[3]), "r"(b[0]), "r"(b[1]));
}
__device__ __forceinline__ void cp16(uint32_t smem_addr, const void* gptr) {
    asm volatile("cp.async.cg.shared.global [%0], [%1], 16;"
                 :: "r"(smem_addr), "l"(gptr));
}
__device__ __forceinline__ void ldsm_x2_trans(uint32_t& r0, uint32_t& r1, uint32_t addr) {
    asm volatile("ldmatrix.sync.aligned.m8n8.x2.trans.shared.b16 {%0,%1}, [%2];"
                 : "=r"(r0), "=r"(r1) : "r"(addr));
}

// ---------------- fused convert (3 tensors) + rope table --------------------
// Each thread converts ONE quad = 8 fp16 values, so counts are R*C/8.
#define NQ_H   (TT * HID / 8)             // 1048576
#define NQ_W   (QKVO * HID / 8)           // 3145728
#define NQ_O   (HID * QSZ / 8)            // 2097152
#define N_ROPE (TT * 32)                  // 65536
#define CONV_TOTAL (NQ_H + NQ_W + NQ_O + N_ROPE)   // 6356992 = 24832*256

__device__ __forceinline__ void conv_one(
    const float* __restrict__ src, uint32_t* __restrict__ dst, int R, int C, int q)
{
    const int lane = q & 31;
    const int t2 = q >> 5;
    const int row16 = t2 % (R >> 4);
    const int k16   = t2 / (R >> 4);
    const int g = lane >> 2, t = lane & 3;
    const size_t r = row16 * 16 + g;
    const size_t c = k16 * 16 + 2 * t;
    const float* p0 = src + r * C + c;
    const float* p1 = src + (r + 8) * C + c;
    uint4 o;
    o.x = packh2(p0[0], p0[1]);
    o.y = packh2(p1[0], p1[1]);
    o.z = packh2(p0[8], p0[9]);
    o.w = packh2(p1[8], p1[9]);
    *(uint4*)&dst[(size_t)q * 4] = o;
}

__global__ __launch_bounds__(256) void conv_all_kernel(
    const float* __restrict__ hidden, const float* __restrict__ w_qkv,
    const float* __restrict__ w_o)
{
    const int gidx = blockIdx.x * 256 + threadIdx.x;
    if (gidx < NQ_H) {
        conv_one(hidden, g_h16, TT, HID, gidx);
    } else if (gidx < NQ_H + NQ_W) {
        conv_one(w_qkv, g_wqkv16, QKVO, HID, gidx - NQ_H);
    } else if (gidx < NQ_H + NQ_W + NQ_O) {
        conv_one(w_o, g_wo16, HID, QSZ, gidx - NQ_H - NQ_W);
    } else if (gidx < CONV_TOTAL) {
        const int idx = gidx - NQ_H - NQ_W - NQ_O;
        const int t = idx >> 5, i = idx & 31;
        const float freq = powf(10000.0f, -(float)i * (1.0f / 32.0f));
        float sn, cs;
        sincosf((float)t * freq, &sn, &cs);
        g_rope[t * 64 + 2 * i]     = cs;
        g_rope[t * 64 + 2 * i + 1] = sn;
    }
}

// ---------------- fp16 quad GEMM: 128x128 tile, 2 CTA/SM, 6-stage -----------
// Two 32-k tiles per barrier: wait + sync once, prefetch 2, compute 2.
#define GEMM_SMEM (6 * 16384)   // 98304 B; also covers EPI1 staging (66560)
template <int EPI>
__global__ __launch_bounds__(256, 2) void gemm_h16(
    const uint32_t* __restrict__ Aq, const uint32_t* __restrict__ Bq,
    const float* __restrict__ bias, float* __restrict__ C,
    const float* __restrict__ qnw, const float* __restrict__ knw,
    int M, int N, int K)
{
    extern __shared__ uint32_t sm[];
    const int tid  = threadIdx.x;
    const int lane = tid & 31;
    const int warp = tid >> 5;
    const int wm = (warp >> 2) * 64;
    const int wn = (warp & 3) * 32;
    const int m0 = blockIdx.y * 128, n0 = blockIdx.x * 128;
    const int g = lane >> 2, t4 = lane & 3;

    const uint32_t smem_base = (uint32_t)__cvta_generic_to_shared(sm);
    const uint32_t dA0 = smem_base + (warp * 32 + lane) * 16;
    const uint32_t dA1 = smem_base + ((8 + warp) * 32 + lane) * 16;
    const uint32_t dB0 = smem_base + 8192 + (warp * 32 + lane) * 16;
    const uint32_t dB1 = smem_base + 8192 + ((8 + warp) * 32 + lane) * 16;
    const uint32_t* srcA = Aq + (size_t)(m0 / 16 + warp) * 128 + lane * 4;
    const uint32_t* srcB = Bq + (size_t)(n0 / 16 + warp) * 128 + lane * 4;
    const size_t sA = (size_t)M * 8;
    const size_t sB = (size_t)N * 8;

    float acc[4][4][4];
#pragma unroll
    for (int i = 0; i < 4; i++)
#pragma unroll
        for (int j = 0; j < 4; j++)
#pragma unroll
            for (int c = 0; c < 4; c++) acc[i][j][c] = 0.f;

#define ISSUE(stage, k16s)                                               \
    do {                                                                 \
        const uint32_t so = (stage) * 16384;                             \
        cp16(dA0 + so, srcA + (size_t)(k16s) * sA);                      \
        cp16(dA1 + so, srcA + (size_t)((k16s) + 1) * sA);                \
        cp16(dB0 + so, srcB + (size_t)(k16s) * sB);                      \
        cp16(dB1 + so, srcB + (size_t)((k16s) + 1) * sB);                \
        asm volatile("cp.async.commit_group;");                          \
    } while (0)

#define COMPUTE_TILE(bufidx)                                                  \
    do {                                                                      \
        const uint32_t* As = sm + (bufidx) * 4096;                            \
        const uint32_t* Bs = As + 2048;                                       \
        _Pragma("unroll")                                                     \
        for (int s = 0; s < 2; s++) {                                         \
            uint4 afq[4];                                                     \
            const uint32_t* ab = As + ((s * 8 + arb) * 32 + lane) * 4;        \
            _Pragma("unroll")                                                 \
            for (int mi = 0; mi < 4; mi++)                                    \
                afq[mi] = *(const uint4*)(ab + mi * 128);                     \
            const uint32_t* bb = Bs + ((s * 8 + bcb) * 32 + lane) * 4;        \
            const uint4 bq0 = *(const uint4*)bb;                              \
            const uint4 bq1 = *(const uint4*)(bb + 128);                      \
            const uint32_t b0[2] = {bq0.x, bq0.z};                            \
            const uint32_t b1[2] = {bq0.y, bq0.w};                            \
            const uint32_t b2[2] = {bq1.x, bq1.z};                            \
            const uint32_t b3[2] = {bq1.y, bq1.w};                            \
            _Pragma("unroll")                                                 \
            for (int mi = 0; mi < 4; mi++) {                                  \
                const uint32_t a[4] = {afq[mi].x, afq[mi].y,                  \
                                       afq[mi].z, afq[mi].w};                 \
                mma_f16(acc[mi][0], a, b0);                                   \
                mma_f16(acc[mi][1], a, b1);                                   \
                mma_f16(acc[mi][2], a, b2);                                   \
                mma_f16(acc[mi][3], a, b3);                                   \
            }                                                                 \
        }                                                                     \
    } while (0)

    const int nkt = K / 32;
    ISSUE(0, 0);
    ISSUE(1, 2);
    ISSUE(2, 4);
    ISSUE(3, 6);

    const int arb = (warp >> 2) * 4;
    const int bcb = (warp & 3) * 2;

    for (int i = 0; i < nkt; i += 2) {
        if (i + 2 < nkt) { asm volatile("cp.async.wait_group 2;"); }
        else             { asm volatile("cp.async.wait_group 0;"); }
        __syncthreads();
        if (i + 4 < nkt) ISSUE((i + 4) % 6, 2 * (i + 4));
        if (i + 5 < nkt) ISSUE((i + 5) % 6, 2 * (i + 5));
        COMPUTE_TILE(i % 6);
        COMPUTE_TILE((i + 1) % 6);
    }
#undef ISSUE
#undef COMPUTE_TILE

    if (EPI == 0) {
#pragma unroll
        for (int mi = 0; mi < 4; mi++) {
            const int row = m0 + wm + mi * 16 + g;
#pragma unroll
            for (int ni = 0; ni < 4; ni++) {
                const int col = n0 + wn + ni * 8 + 2 * t4;
                float2 v0 = make_float2(acc[mi][ni][0], acc[mi][ni][1]);
                float2 v1 = make_float2(acc[mi][ni][2], acc[mi][ni][3]);
                *(float2*)&C[(size_t)row * N + col] = v0;
                *(float2*)&C[(size_t)(row + 8) * N + col] = v1;
            }
        }
        return;
    }

    // ---- EPI == 1: fused bias + RMSNorm + RoPE + fp16 pack ----
    float* stg = (float*)sm;    // [128][130]
    __syncthreads();
#pragma unroll
    for (int mi = 0; mi < 4; mi++) {
        const int row = wm + mi * 16 + g;
#pragma unroll
        for (int ni = 0; ni < 4; ni++) {
            const int col = wn + ni * 8 + 2 * t4;
            const float b0 = bias[n0 + col], b1 = bias[n0 + col + 1];
            stg[row * 130 + col]     = acc[mi][ni][0] + b0;
            stg[row * 130 + col + 1] = acc[mi][ni][1] + b1;
            stg[(row + 8) * 130 + col]     = acc[mi][ni][2] + b0;
            stg[(row + 8) * 130 + col + 1] = acc[mi][ni][3] + b1;
        }
    }
    __syncthreads();

    const int r = tid >> 1, h2 = tid & 1;
    const int tok = m0 + r;
    const int nh = n0 >> 7;
    float y[64];
    const float* rp = stg + r * 130 + h2 * 64;
#pragma unroll
    for (int i = 0; i < 32; i++) {
        float2 f = *(const float2*)(rp + 2 * i);
        y[2 * i] = f.x; y[2 * i + 1] = f.y;
    }
    float ssq = 0.f;
#pragma unroll
    for (int j = 0; j < 64; j++) ssq += y[j] * y[j];
    ssq += __shfl_xor_sync(0xffffffffu, ssq, 1);

    if (nh < 40) {
        const float rms = rsqrtf(ssq * (1.0f / HD) + 1e-5f);
        const float* wv = (nh < NH ? qnw : knw) + h2 * 64;
#pragma unroll
        for (int j = 0; j < 64; j++) y[j] *= rms * wv[j];
        if (h2 == 0) {
            const float* rt = g_rope + tok * 64;
#pragma unroll
            for (int d = 0; d < 32; d++) {
                const float cs = rt[2 * d], sn = rt[2 * d + 1];
                const float a0 = y[d] * cs - y[d + 32] * sn;
                const float a1 = y[d + 32] * cs + y[d] * sn;
                y[d] = a0; y[d + 32] = a1;
            }
        }
        if (nh < NH) {
#pragma unroll
            for (int j = 0; j < 64; j++) y[j] *= 0.0883883476483184f;
        }
    }

    uint32_t* dst;
    if (nh < NH)      dst = g_qh + (size_t)tok * (QSZ / 2) + nh * 64 + h2 * 32;
    else if (nh < 40) dst = g_kh + (size_t)tok * (KVSZ / 2) + (nh - NH) * 64 + h2 * 32;
    else              dst = g_vh + (size_t)tok * (KVSZ / 2) + (nh - 40) * 64 + h2 * 32;
#pragma unroll
    for (int u = 0; u < 8; u++) {
        uint4 o;
        o.x = packh2(y[8 * u + 0], y[8 * u + 1]);
        o.y = packh2(y[8 * u + 2], y[8 * u + 3]);
        o.z = packh2(y[8 * u + 4], y[8 * u + 5]);
        o.w = packh2(y[8 * u + 6], y[8 * u + 7]);
        ((uint4*)dst)[u] = o;
    }
}

// ---------------- fp16 tensor-core causal flash attention -------------------
#define AQS 68
#define K_OFF 0
#define V_OFF (64 * AQS)
#define ATTN_SMEM (2 * 64 * AQS * 4)   // 34816 B

__global__ __launch_bounds__(128, 3) void attn_h16_kernel()
{
    extern __shared__ uint32_t smem_u[];
    const int tid  = threadIdx.x;
    const int lane = tid & 31;
    const int warp = tid >> 5;
    const int g    = lane >> 2;
    const int t4   = lane & 3;
    const int wq0  = warp * 16;
    const int bx = blockIdx.x, h = blockIdx.y, kvh = h >> 2;

    const uint32_t sb = (uint32_t)__cvta_generic_to_shared(smem_u);
    const uint32_t vb = sb + (V_OFF + (lane & 15) * AQS) * 4;

    uint32_t qa[8][4];
    {
        const uint32_t* q0 = &g_qh[(size_t)(bx * 64 + wq0 + g) * (QSZ / 2) + h * 64];
        const uint32_t* q1 = &g_qh[(size_t)(bx * 64 + wq0 + g + 8) * (QSZ / 2) + h * 64];
#pragma unroll
        for (int kb = 0; kb < 8; kb++) {
            qa[kb][0] = q0[kb * 8 + t4];
            qa[kb][1] = q1[kb * 8 + t4];
            qa[kb][2] = q0[kb * 8 + t4 + 4];
            qa[kb][3] = q1[kb * 8 + t4 + 4];
        }
    }

    float m0 = -1e30f, m1 = -1e30f, l0 = 0.f, l1 = 0.f;
    float acc_o[16][4];
#pragma unroll
    for (int nb = 0; nb < 16; nb++)
#pragma unroll
        for (int c = 0; c < 4; c++) acc_o[nb][c] = 0.f;

    for (int kt = 0; kt <= bx; kt++) {
        __syncthreads();
        for (int i = tid; i < 1024; i += 128) {
            const int r = i >> 4, w4 = (i & 15) << 2;
            const size_t goff = (size_t)(kt * 64 + r) * (KVSZ / 2) + kvh * 64 + w4;
            uint4 kw = *(const uint4*)&g_kh[goff];
            *(uint4*)&smem_u[K_OFF + r * AQS + w4] = kw;
            uint4 vw = *(const uint4*)&g_vh[goff];
            *(uint4*)&smem_u[V_OFF + r * AQS + w4] = vw;
        }
        __syncthreads();

        float s[8][4];
#pragma unroll
        for (int nb = 0; nb < 8; nb++)
#pragma unroll
            for (int c = 0; c < 4; c++) s[nb][c] = 0.f;

#pragma unroll
        for (int kb = 0; kb < 8; kb++) {
#pragma unroll
            for (int nb = 0; nb < 8; nb++) {
                uint32_t b[2];
                b[0] = smem_u[K_OFF + (nb * 8 + g) * AQS + kb * 8 + t4];
                b[1] = smem_u[K_OFF + (nb * 8 + g) * AQS + kb * 8 + t4 + 4];
                mma_f16(s[nb], qa[kb], b);
            }
        }

        if (kt == bx) {
            const int r0 = wq0 + g, r1 = r0 + 8;
#pragma unroll
            for (int nb = 0; nb < 8; nb++) {
                const int c = nb * 8 + 2 * t4;
                if (c     > r0) s[nb][0] = -1e30f;
                if (c + 1 > r0) s[nb][1] = -1e30f;
                if (c     > r1) s[nb][2] = -1e30f;
                if (c + 1 > r1) s[nb][3] = -1e30f;
            }
        }

        float mx0 = -1e30f, mx1 = -1e30f;
#pragma unroll
        for (int nb = 0; nb < 8; nb++) {
            mx0 = fmaxf(mx0, fmaxf(s[nb][0], s[nb][1]));
            mx1 = fmaxf(mx1, fmaxf(s[nb][2], s[nb][3]));
        }
        mx0 = fmaxf(mx0, __shfl_xor_sync(0xffffffffu, mx0, 1));
        mx0 = fmaxf(mx0, __shfl_xor_sync(0xffffffffu, mx0, 2));
        mx1 = fmaxf(mx1, __shfl_xor_sync(0xffffffffu, mx1, 1));
        mx1 = fmaxf(mx1, __shfl_xor_sync(0xffffffffu, mx1, 2));
        const float mn0 = fmaxf(m0, mx0), mn1 = fmaxf(m1, mx1);
        const float cr0 = __expf(m0 - mn0), cr1 = __expf(m1 - mn1);
        float rs0 = 0.f, rs1 = 0.f;
        uint32_t ph0[8], ph1[8];
#pragma unroll
        for (int nb = 0; nb < 8; nb++) {
            float p0 = __expf(s[nb][0] - mn0);
            float p1 = __expf(s[nb][1] - mn0);
            float p2 = __expf(s[nb][2] - mn1);
            float p3 = __expf(s[nb][3] - mn1);
            rs0 += p0 + p1; rs1 += p2 + p3;
            ph0[nb] = packh2(p0, p1);
            ph1[nb] = packh2(p2, p3);
        }
        rs0 += __shfl_xor_sync(0xffffffffu, rs0, 1);
        rs0 += __shfl_xor_sync(0xffffffffu, rs0, 2);
        rs1 += __shfl_xor_sync(0xffffffffu, rs1, 1);
        rs1 += __shfl_xor_sync(0xffffffffu, rs1, 2);
        l0 = l0 * cr0 + rs0; l1 = l1 * cr1 + rs1;
        m0 = mn0; m1 = mn1;

#pragma unroll
        for (int nb = 0; nb < 16; nb++) {
            acc_o[nb][0] *= cr0; acc_o[nb][1] *= cr0;
            acc_o[nb][2] *= cr1; acc_o[nb][3] *= cr1;
        }

#pragma unroll
        for (int kb = 0; kb < 4; kb++) {
            const uint32_t a[4] = {ph0[2 * kb], ph1[2 * kb],
                                   ph0[2 * kb + 1], ph1[2 * kb + 1]};
            const uint32_t vkb = vb + kb * 16 * AQS * 4;
#pragma unroll
            for (int nb = 0; nb < 16; nb++) {
                uint32_t b[2];
                ldsm_x2_trans(b[0], b[1], vkb + nb * 16);
                mma_f16(acc_o[nb], a, b);
            }
        }
    }

    const float il0 = 1.0f / l0, il1 = 1.0f / l1;
    const int row16 = bx * 4 + warp;
#pragma unroll
    for (int nbp = 0; nbp < 8; nbp++) {
        const int nbe = 2 * nbp, nbo = 2 * nbp + 1;
        const int k16 = h * 8 + nbp;
        uint4 o;
        o.x = packh2(acc_o[nbe][0] * il0, acc_o[nbe][1] * il0);
        o.y = packh2(acc_o[nbe][2] * il1, acc_o[nbe][3] * il1);
        o.z = packh2(acc_o[nbo][0] * il0, acc_o[nbo][1] * il0);
        o.w = packh2(acc_o[nbo][2] * il1, acc_o[nbo][3] * il1);
        const size_t quad = ((size_t)k16 * (TT / 16) + row16) * 32 + lane;
        *(uint4*)&g_attnq16[quad * 4] = o;
    }
}

// ---------------- launch ----------------
extern "C" void kernel_launch(void* const* d_in, const int* in_sizes, int n_in,
                              void* d_out, int out_size)
{
    const float* hidden = (const float*)d_in[1];
    const float* w_qkv  = (const float*)d_in[2];
    const float* b_qkv  = (const float*)d_in[3];
    const float* qnw    = (const float*)d_in[4];
    const float* knw    = (const float*)d_in[5];
    const float* w_o    = (const float*)d_in[6];
    float* out = (float*)d_out;

    uint32_t *attnq_s, *h16_s, *wqkv16_s, *wo16_s;
    cudaGetSymbolAddress((void**)&attnq_s, g_attnq16);
    cudaGetSymbolAddress((void**)&h16_s, g_h16);
    cudaGetSymbolAddress((void**)&wqkv16_s, g_wqkv16);
    cudaGetSymbolAddress((void**)&wo16_s, g_wo16);

    // 0) fused conversion (hidden, w_qkv, w_o) + rope table, one launch
    conv_all_kernel<<<CONV_TOTAL / 256, 256>>>(hidden, w_qkv, w_o);

    cudaFuncSetAttribute(gemm_h16<1>,
                         cudaFuncAttributeMaxDynamicSharedMemorySize, GEMM_SMEM);
    cudaFuncSetAttribute(gemm_h16<0>,
                         cudaFuncAttributeMaxDynamicSharedMemorySize, GEMM_SMEM);

    // 1) QKV projection + fused bias/norm/rope/pack
    gemm_h16<1><<<dim3(QKVO / 128, TT / 128), 256, GEMM_SMEM>>>(
        h16_s, wqkv16_s, b_qkv, nullptr, qnw, knw, TT, QKVO, HID);

    // 2) causal GQA flash attention
    cudaFuncSetAttribute(attn_h16_kernel,
                         cudaFuncAttributeMaxDynamicSharedMemorySize, ATTN_SMEM);
    attn_h16_kernel<<<dim3(TT / 64, NH), 128, ATTN_SMEM>>>();

    // 3) output projection
    gemm_h16<0><<<dim3(HID / 128, TT / 128), 256, GEMM_SMEM>>>(
        attnq_s, wo16_s, nullptr, out, nullptr, nullptr, TT, HID, QSZ);
}

// round 15
// speedup vs baseline: 1.0921x; 1.0497x over previous
#include <cuda_runtime.h>
#include <cuda_fp16.h>
#include <math.h>
#include <stdint.h>

#define TT   2048
#define HID  4096
#define NH   32
#define NKV  8
#define HD   128
#define QSZ  (NH * HD)          // 4096
#define KVSZ (NKV * HD)         // 1024
#define QKVO (QSZ + 2 * KVSZ)   // 6144

// ---------------- device scratch (allocation-free) ----------------
__device__ uint32_t g_qh[TT * QSZ / 2];        // normed+roped+scaled q (half2)
__device__ uint32_t g_kh[TT * KVSZ / 2];       // normed+roped k (half2)
__device__ uint32_t g_vh[TT * KVSZ / 2];       // v (half2)
__device__ uint32_t g_attnq16[TT * QSZ / 2];   // attn out, fp16 quad layout
__device__ uint32_t g_h16[TT * HID / 2];       // hidden, fp16 quad layout
__device__ uint32_t g_wqkv16[QKVO * HID / 2];  // w_qkv,  fp16 quad layout
__device__ uint32_t g_wo16[HID * QSZ / 2];     // w_o,    fp16 quad layout
__device__ float    g_rope[TT * 64];           // cos/sin table per (t, i)

// ---------------- helpers ----------------
__device__ __forceinline__ uint32_t packh2(float a, float b) {
    __half2 h = __floats2half2_rn(a, b);
    return *(uint32_t*)&h;
}
__device__ __forceinline__ void mma_f16(float* d, const uint32_t* a, const uint32_t* b) {
    asm volatile(
        "mma.sync.aligned.m16n8k16.row.col.f32.f16.f16.f32 "
        "{%0,%1,%2,%3},{%4,%5,%6,%7},{%8,%9},{%0,%1,%2,%3};"
        : "+f"(d[0]), "+f"(d[1]), "+f"(d[2]), "+f"(d[3])
        : "r"(a[0]), "r"(a[1]), "r"(a[2]), "r"(a[3]), "r"(b[0]), "r"(b[1]));
}
__device__ __forceinline__ void cp16(uint32_t smem_addr, const void* gptr) {
    asm volatile("cp.async.cg.shared.global [%0], [%1], 16;"
                 :: "r"(smem_addr), "l"(gptr));
}
__device__ __forceinline__ void ldsm_x2_trans(uint32_t& r0, uint32_t& r1, uint32_t addr) {
    asm volatile("ldmatrix.sync.aligned.m8n8.x2.trans.shared.b16 {%0,%1}, [%2];"
                 : "=r"(r0), "=r"(r1) : "r"(addr));
}

// ---------------- fused convert (3 tensors) + rope table --------------------
#define NQ_H   (TT * HID / 8)             // 1048576
#define NQ_W   (QKVO * HID / 8)           // 3145728
#define NQ_O   (HID * QSZ / 8)            // 2097152
#define N_ROPE (TT * 32)                  // 65536
#define CONV_TOTAL (NQ_H + NQ_W + NQ_O + N_ROPE)   // 6356992 = 24832*256

__device__ __forceinline__ void conv_one(
    const float* __restrict__ src, uint32_t* __restrict__ dst, int R, int C, int q)
{
    const int lane = q & 31;
    const int t2 = q >> 5;
    const int row16 = t2 % (R >> 4);
    const int k16   = t2 / (R >> 4);
    const int g = lane >> 2, t = lane & 3;
    const size_t r = row16 * 16 + g;
    const size_t c = k16 * 16 + 2 * t;
    const float* p0 = src + r * C + c;
    const float* p1 = src + (r + 8) * C + c;
    uint4 o;
    o.x = packh2(p0[0], p0[1]);
    o.y = packh2(p1[0], p1[1]);
    o.z = packh2(p0[8], p0[9]);
    o.w = packh2(p1[8], p1[9]);
    *(uint4*)&dst[(size_t)q * 4] = o;
}

__global__ __launch_bounds__(256) void conv_all_kernel(
    const float* __restrict__ hidden, const float* __restrict__ w_qkv,
    const float* __restrict__ w_o)
{
    const int gidx = blockIdx.x * 256 + threadIdx.x;
    if (gidx < NQ_H) {
        conv_one(hidden, g_h16, TT, HID, gidx);
    } else if (gidx < NQ_H + NQ_W) {
        conv_one(w_qkv, g_wqkv16, QKVO, HID, gidx - NQ_H);
    } else if (gidx < NQ_H + NQ_W + NQ_O) {
        conv_one(w_o, g_wo16, HID, QSZ, gidx - NQ_H - NQ_W);
    } else if (gidx < CONV_TOTAL) {
        const int idx = gidx - NQ_H - NQ_W - NQ_O;
        const int t = idx >> 5, i = idx & 31;
        const float freq = powf(10000.0f, -(float)i * (1.0f / 32.0f));
        float sn, cs;
        sincosf((float)t * freq, &sn, &cs);
        g_rope[t * 64 + 2 * i]     = cs;
        g_rope[t * 64 + 2 * i + 1] = sn;
    }
}

// ---------------- fp16 quad GEMM: 128x128 tile, 2 CTA/SM, 6-stage -----------
#define GEMM_SMEM (6 * 16384)
template <int EPI>
__global__ __launch_bounds__(256, 2) void gemm_h16(
    const uint32_t* __restrict__ Aq, const uint32_t* __restrict__ Bq,
    const float* __restrict__ bias, float* __restrict__ C,
    const float* __restrict__ qnw, const float* __restrict__ knw,
    int M, int N, int K)
{
    extern __shared__ uint32_t sm[];
    const int tid  = threadIdx.x;
    const int lane = tid & 31;
    const int warp = tid >> 5;
    const int wm = (warp >> 2) * 64;
    const int wn = (warp & 3) * 32;
    const int m0 = blockIdx.y * 128, n0 = blockIdx.x * 128;
    const int g = lane >> 2, t4 = lane & 3;

    const uint32_t smem_base = (uint32_t)__cvta_generic_to_shared(sm);
    const uint32_t dA0 = smem_base + (warp * 32 + lane) * 16;
    const uint32_t dA1 = smem_base + ((8 + warp) * 32 + lane) * 16;
    const uint32_t dB0 = smem_base + 8192 + (warp * 32 + lane) * 16;
    const uint32_t dB1 = smem_base + 8192 + ((8 + warp) * 32 + lane) * 16;
    const uint32_t* srcA = Aq + (size_t)(m0 / 16 + warp) * 128 + lane * 4;
    const uint32_t* srcB = Bq + (size_t)(n0 / 16 + warp) * 128 + lane * 4;
    const size_t sA = (size_t)M * 8;
    const size_t sB = (size_t)N * 8;

    float acc[4][4][4];
#pragma unroll
    for (int i = 0; i < 4; i++)
#pragma unroll
        for (int j = 0; j < 4; j++)
#pragma unroll
            for (int c = 0; c < 4; c++) acc[i][j][c] = 0.f;

#define ISSUE(stage, k16s)                                               \
    do {                                                                 \
        const uint32_t so = (stage) * 16384;                             \
        cp16(dA0 + so, srcA + (size_t)(k16s) * sA);                      \
        cp16(dA1 + so, srcA + (size_t)((k16s) + 1) * sA);                \
        cp16(dB0 + so, srcB + (size_t)(k16s) * sB);                      \
        cp16(dB1 + so, srcB + (size_t)((k16s) + 1) * sB);                \
        asm volatile("cp.async.commit_group;");                          \
    } while (0)

#define COMPUTE_TILE(bufidx)                                                  \
    do {                                                                      \
        const uint32_t* As = sm + (bufidx) * 4096;                            \
        const uint32_t* Bs = As + 2048;                                       \
        _Pragma("unroll")                                                     \
        for (int s = 0; s < 2; s++) {                                         \
            uint4 afq[4];                                                     \
            const uint32_t* ab = As + ((s * 8 + arb) * 32 + lane) * 4;        \
            _Pragma("unroll")                                                 \
            for (int mi = 0; mi < 4; mi++)                                    \
                afq[mi] = *(const uint4*)(ab + mi * 128);                     \
            const uint32_t* bb = Bs + ((s * 8 + bcb) * 32 + lane) * 4;        \
            const uint4 bq0 = *(const uint4*)bb;                              \
            const uint4 bq1 = *(const uint4*)(bb + 128);                      \
            const uint32_t b0[2] = {bq0.x, bq0.z};                            \
            const uint32_t b1[2] = {bq0.y, bq0.w};                            \
            const uint32_t b2[2] = {bq1.x, bq1.z};                            \
            const uint32_t b3[2] = {bq1.y, bq1.w};                            \
            _Pragma("unroll")                                                 \
            for (int mi = 0; mi < 4; mi++) {                                  \
                const uint32_t a[4] = {afq[mi].x, afq[mi].y,                  \
                                       afq[mi].z, afq[mi].w};                 \
                mma_f16(acc[mi][0], a, b0);                                   \
                mma_f16(acc[mi][1], a, b1);                                   \
                mma_f16(acc[mi][2], a, b2);                                   \
                mma_f16(acc[mi][3], a, b3);                                   \
            }                                                                 \
        }                                                                     \
    } while (0)

    const int nkt = K / 32;
    ISSUE(0, 0);
    ISSUE(1, 2);
    ISSUE(2, 4);
    ISSUE(3, 6);

    const int arb = (warp >> 2) * 4;
    const int bcb = (warp & 3) * 2;

    for (int i = 0; i < nkt; i += 2) {
        if (i + 2 < nkt) { asm volatile("cp.async.wait_group 2;"); }
        else             { asm volatile("cp.async.wait_group 0;"); }
        __syncthreads();
        if (i + 4 < nkt) ISSUE((i + 4) % 6, 2 * (i + 4));
        if (i + 5 < nkt) ISSUE((i + 5) % 6, 2 * (i + 5));
        COMPUTE_TILE(i % 6);
        COMPUTE_TILE((i + 1) % 6);
    }
#undef ISSUE
#undef COMPUTE_TILE

    if (EPI == 0) {
#pragma unroll
        for (int mi = 0; mi < 4; mi++) {
            const int row = m0 + wm + mi * 16 + g;
#pragma unroll
            for (int ni = 0; ni < 4; ni++) {
                const int col = n0 + wn + ni * 8 + 2 * t4;
                float2 v0 = make_float2(acc[mi][ni][0], acc[mi][ni][1]);
                float2 v1 = make_float2(acc[mi][ni][2], acc[mi][ni][3]);
                *(float2*)&C[(size_t)row * N + col] = v0;
                *(float2*)&C[(size_t)(row + 8) * N + col] = v1;
            }
        }
        return;
    }

    // ---- EPI == 1: fused bias + RMSNorm + RoPE + fp16 pack ----
    float* stg = (float*)sm;    // [128][130]
    __syncthreads();
#pragma unroll
    for (int mi = 0; mi < 4; mi++) {
        const int row = wm + mi * 16 + g;
#pragma unroll
        for (int ni = 0; ni < 4; ni++) {
            const int col = wn + ni * 8 + 2 * t4;
            const float b0 = bias[n0 + col], b1 = bias[n0 + col + 1];
            stg[row * 130 + col]     = acc[mi][ni][0] + b0;
            stg[row * 130 + col + 1] = acc[mi][ni][1] + b1;
            stg[(row + 8) * 130 + col]     = acc[mi][ni][2] + b0;
            stg[(row + 8) * 130 + col + 1] = acc[mi][ni][3] + b1;
        }
    }
    __syncthreads();

    const int r = tid >> 1, h2 = tid & 1;
    const int tok = m0 + r;
    const int nh = n0 >> 7;
    float y[64];
    const float* rp = stg + r * 130 + h2 * 64;
#pragma unroll
    for (int i = 0; i < 32; i++) {
        float2 f = *(const float2*)(rp + 2 * i);
        y[2 * i] = f.x; y[2 * i + 1] = f.y;
    }
    float ssq = 0.f;
#pragma unroll
    for (int j = 0; j < 64; j++) ssq += y[j] * y[j];
    ssq += __shfl_xor_sync(0xffffffffu, ssq, 1);

    if (nh < 40) {
        const float rms = rsqrtf(ssq * (1.0f / HD) + 1e-5f);
        const float* wv = (nh < NH ? qnw : knw) + h2 * 64;
#pragma unroll
        for (int j = 0; j < 64; j++) y[j] *= rms * wv[j];
        if (h2 == 0) {
            const float* rt = g_rope + tok * 64;
#pragma unroll
            for (int d = 0; d < 32; d++) {
                const float cs = rt[2 * d], sn = rt[2 * d + 1];
                const float a0 = y[d] * cs - y[d + 32] * sn;
                const float a1 = y[d + 32] * cs + y[d] * sn;
                y[d] = a0; y[d + 32] = a1;
            }
        }
        if (nh < NH) {
            // fold 1/sqrt(HD) * log2(e)  (softmax runs in exp2 domain)
#pragma unroll
            for (int j = 0; j < 64; j++) y[j] *= 0.1275186896f;
        }
    }

    uint32_t* dst;
    if (nh < NH)      dst = g_qh + (size_t)tok * (QSZ / 2) + nh * 64 + h2 * 32;
    else if (nh < 40) dst = g_kh + (size_t)tok * (KVSZ / 2) + (nh - NH) * 64 + h2 * 32;
    else              dst = g_vh + (size_t)tok * (KVSZ / 2) + (nh - 40) * 64 + h2 * 32;
#pragma unroll
    for (int u = 0; u < 8; u++) {
        uint4 o;
        o.x = packh2(y[8 * u + 0], y[8 * u + 1]);
        o.y = packh2(y[8 * u + 2], y[8 * u + 3]);
        o.z = packh2(y[8 * u + 4], y[8 * u + 5]);
        o.w = packh2(y[8 * u + 6], y[8 * u + 7]);
        ((uint4*)dst)[u] = o;
    }
}

// ---------------- fp16 tensor-core causal flash attention -------------------
// LPT order: grid=(NH, T/64), bx = reversed y (longest CTAs launch first).
// Softmax in exp2 domain (log2e folded into q scale).
#define AQS 68
#define K_OFF 0
#define V_OFF (64 * AQS)
#define ATTN_SMEM (2 * 64 * AQS * 4)   // 34816 B

__global__ __launch_bounds__(128, 3) void attn_h16_kernel()
{
    extern __shared__ uint32_t smem_u[];
    const int tid  = threadIdx.x;
    const int lane = tid & 31;
    const int warp = tid >> 5;
    const int g    = lane >> 2;
    const int t4   = lane & 3;
    const int wq0  = warp * 16;
    const int h  = blockIdx.x;                       // head
    const int bx = gridDim.y - 1 - blockIdx.y;       // q tile, longest first
    const int kvh = h >> 2;

    const uint32_t sb = (uint32_t)__cvta_generic_to_shared(smem_u);
    const uint32_t vb = sb + (V_OFF + (lane & 15) * AQS) * 4;

    uint32_t qa[8][4];
    {
        const uint32_t* q0 = &g_qh[(size_t)(bx * 64 + wq0 + g) * (QSZ / 2) + h * 64];
        const uint32_t* q1 = &g_qh[(size_t)(bx * 64 + wq0 + g + 8) * (QSZ / 2) + h * 64];
#pragma unroll
        for (int kb = 0; kb < 8; kb++) {
            qa[kb][0] = q0[kb * 8 + t4];
            qa[kb][1] = q1[kb * 8 + t4];
            qa[kb][2] = q0[kb * 8 + t4 + 4];
            qa[kb][3] = q1[kb * 8 + t4 + 4];
        }
    }

    float m0 = -1e30f, m1 = -1e30f, l0 = 0.f, l1 = 0.f;
    float acc_o[16][4];
#pragma unroll
    for (int nb = 0; nb < 16; nb++)
#pragma unroll
        for (int c = 0; c < 4; c++) acc_o[nb][c] = 0.f;

    for (int kt = 0; kt <= bx; kt++) {
        __syncthreads();
        for (int i = tid; i < 1024; i += 128) {
            const int r = i >> 4, w4 = (i & 15) << 2;
            const size_t goff = (size_t)(kt * 64 + r) * (KVSZ / 2) + kvh * 64 + w4;
            uint4 kw = *(const uint4*)&g_kh[goff];
            *(uint4*)&smem_u[K_OFF + r * AQS + w4] = kw;
            uint4 vw = *(const uint4*)&g_vh[goff];
            *(uint4*)&smem_u[V_OFF + r * AQS + w4] = vw;
        }
        __syncthreads();

        float s[8][4];
#pragma unroll
        for (int nb = 0; nb < 8; nb++)
#pragma unroll
            for (int c = 0; c < 4; c++) s[nb][c] = 0.f;

#pragma unroll
        for (int kb = 0; kb < 8; kb++) {
#pragma unroll
            for (int nb = 0; nb < 8; nb++) {
                uint32_t b[2];
                b[0] = smem_u[K_OFF + (nb * 8 + g) * AQS + kb * 8 + t4];
                b[1] = smem_u[K_OFF + (nb * 8 + g) * AQS + kb * 8 + t4 + 4];
                mma_f16(s[nb], qa[kb], b);
            }
        }

        if (kt == bx) {
            const int r0 = wq0 + g, r1 = r0 + 8;
#pragma unroll
            for (int nb = 0; nb < 8; nb++) {
                const int c = nb * 8 + 2 * t4;
                if (c     > r0) s[nb][0] = -1e30f;
                if (c + 1 > r0) s[nb][1] = -1e30f;
                if (c     > r1) s[nb][2] = -1e30f;
                if (c + 1 > r1) s[nb][3] = -1e30f;
            }
        }

        float mx0 = -1e30f, mx1 = -1e30f;
#pragma unroll
        for (int nb = 0; nb < 8; nb++) {
            mx0 = fmaxf(mx0, fmaxf(s[nb][0], s[nb][1]));
            mx1 = fmaxf(mx1, fmaxf(s[nb][2], s[nb][3]));
        }
        mx0 = fmaxf(mx0, __shfl_xor_sync(0xffffffffu, mx0, 1));
        mx0 = fmaxf(mx0, __shfl_xor_sync(0xffffffffu, mx0, 2));
        mx1 = fmaxf(mx1, __shfl_xor_sync(0xffffffffu, mx1, 1));
        mx1 = fmaxf(mx1, __shfl_xor_sync(0xffffffffu, mx1, 2));
        const float mn0 = fmaxf(m0, mx0), mn1 = fmaxf(m1, mx1);
        const float cr0 = exp2f(m0 - mn0), cr1 = exp2f(m1 - mn1);
        float rs0 = 0.f, rs1 = 0.f;
        uint32_t ph0[8], ph1[8];
#pragma unroll
        for (int nb = 0; nb < 8; nb++) {
            float p0 = exp2f(s[nb][0] - mn0);
            float p1 = exp2f(s[nb][1] - mn0);
            float p2 = exp2f(s[nb][2] - mn1);
            float p3 = exp2f(s[nb][3] - mn1);
            rs0 += p0 + p1; rs1 += p2 + p3;
            ph0[nb] = packh2(p0, p1);
            ph1[nb] = packh2(p2, p3);
        }
        rs0 += __shfl_xor_sync(0xffffffffu, rs0, 1);
        rs0 += __shfl_xor_sync(0xffffffffu, rs0, 2);
        rs1 += __shfl_xor_sync(0xffffffffu, rs1, 1);
        rs1 += __shfl_xor_sync(0xffffffffu, rs1, 2);
        l0 = l0 * cr0 + rs0; l1 = l1 * cr1 + rs1;
        m0 = mn0; m1 = mn1;

#pragma unroll
        for (int nb = 0; nb < 16; nb++) {
            acc_o[nb][0] *= cr0; acc_o[nb][1] *= cr0;
            acc_o[nb][2] *= cr1; acc_o[nb][3] *= cr1;
        }

#pragma unroll
        for (int kb = 0; kb < 4; kb++) {
            const uint32_t a[4] = {ph0[2 * kb], ph1[2 * kb],
                                   ph0[2 * kb + 1], ph1[2 * kb + 1]};
            const uint32_t vkb = vb + kb * 16 * AQS * 4;
#pragma unroll
            for (int nb = 0; nb < 16; nb++) {
                uint32_t b[2];
                ldsm_x2_trans(b[0], b[1], vkb + nb * 16);
                mma_f16(acc_o[nb], a, b);
            }
        }
    }

    const float il0 = 1.0f / l0, il1 = 1.0f / l1;
    const int row16 = bx * 4 + warp;
#pragma unroll
    for (int nbp = 0; nbp < 8; nbp++) {
        const int nbe = 2 * nbp, nbo = 2 * nbp + 1;
        const int k16 = h * 8 + nbp;
        uint4 o;
        o.x = packh2(acc_o[nbe][0] * il0, acc_o[nbe][1] * il0);
        o.y = packh2(acc_o[nbe][2] * il1, acc_o[nbe][3] * il1);
        o.z = packh2(acc_o[nbo][0] * il0, acc_o[nbo][1] * il0);
        o.w = packh2(acc_o[nbo][2] * il1, acc_o[nbo][3] * il1);
        const size_t quad = ((size_t)k16 * (TT / 16) + row16) * 32 + lane;
        *(uint4*)&g_attnq16[quad * 4] = o;
    }
}

// ---------------- launch ----------------
extern "C" void kernel_launch(void* const* d_in, const int* in_sizes, int n_in,
                              void* d_out, int out_size)
{
    const float* hidden = (const float*)d_in[1];
    const float* w_qkv  = (const float*)d_in[2];
    const float* b_qkv  = (const float*)d_in[3];
    const float* qnw    = (const float*)d_in[4];
    const float* knw    = (const float*)d_in[5];
    const float* w_o    = (const float*)d_in[6];
    float* out = (float*)d_out;

    uint32_t *attnq_s, *h16_s, *wqkv16_s, *wo16_s;
    cudaGetSymbolAddress((void**)&attnq_s, g_attnq16);
    cudaGetSymbolAddress((void**)&h16_s, g_h16);
    cudaGetSymbolAddress((void**)&wqkv16_s, g_wqkv16);
    cudaGetSymbolAddress((void**)&wo16_s, g_wo16);

    // 0) fused conversion (hidden, w_qkv, w_o) + rope table
    conv_all_kernel<<<CONV_TOTAL / 256, 256>>>(hidden, w_qkv, w_o);

    cudaFuncSetAttribute(gemm_h16<1>,
                         cudaFuncAttributeMaxDynamicSharedMemorySize, GEMM_SMEM);
    cudaFuncSetAttribute(gemm_h16<0>,
                         cudaFuncAttributeMaxDynamicSharedMemorySize, GEMM_SMEM);

    // 1) QKV projection + fused bias/norm/rope/pack (q scaled incl. log2e)
    gemm_h16<1><<<dim3(QKVO / 128, TT / 128), 256, GEMM_SMEM>>>(
        h16_s, wqkv16_s, b_qkv, nullptr, qnw, knw, TT, QKVO, HID);

    // 2) causal GQA flash attention (LPT ordering, exp2 softmax)
    cudaFuncSetAttribute(attn_h16_kernel,
                         cudaFuncAttributeMaxDynamicSharedMemorySize, ATTN_SMEM);
    attn_h16_kernel<<<dim3(NH, TT / 64), 128, ATTN_SMEM>>>();

    // 3) output projection
    gemm_h16<0><<<dim3(HID / 128, TT / 128), 256, GEMM_SMEM>>>(
        attnq_s, wo16_s, nullptr, out, nullptr, nullptr, TT, HID, QSZ);
}